// round 2
// baseline (speedup 1.0000x reference)
#include <cuda_runtime.h>
#include <cuda_fp16.h>

#define NBLK 128
#define NTHR 256
#define T_STEPS 512
#define PLEN 64

// ---------------- device state (no allocations allowed) ----------------
__device__ __half g_Wp0[128 * 36 * 1024];   // layer0 packed fp16 (K=1152)
__device__ __half g_Wp1[128 * 64 * 1024];   // layer1 packed fp16 (K=2048)
__device__ __half g_Wp2[128 * 64 * 1024];   // layer2 packed fp16 (K=2048)
__device__ float  g_bsum[3 * 4096];
__device__ __half g_In0[64 * 128];          // layer0 input slice (fp16)
__device__ __half g_X1[64 * 1024];          // h0(t) -> layer1 input part
__device__ __half g_X2[64 * 1024];          // h1(t) -> layer2 input part
__device__ __half g_Xfc[64 * 1024];         // h2(t) -> fc input
__device__ __half g_Hst[3][2][64 * 1024];   // double-buffered recurrent h per layer
__device__ float  g_Cst[3 * 64 * 1024];     // cell state fp32
__device__ unsigned g_count;                // barrier arrive counter (stays 0 across launches)
__device__ unsigned g_gen;                  // barrier generation

// ---------------- helpers ----------------
__device__ __forceinline__ float sigf(float v) { return 1.0f / (1.0f + expf(-v)); }

__device__ __forceinline__ unsigned smaddr(const void* p) {
    return (unsigned)__cvta_generic_to_shared(p);
}
__device__ __forceinline__ void cp16(unsigned dst, const void* src) {
    asm volatile("cp.async.cg.shared.global [%0], [%1], 16;" :: "r"(dst), "l"(src));
}
__device__ __forceinline__ void cp_commit() { asm volatile("cp.async.commit_group;"); }

__device__ __forceinline__ void mma16816(float c[4],
    unsigned a0, unsigned a1, unsigned a2, unsigned a3, unsigned b0, unsigned b1) {
    asm volatile(
        "mma.sync.aligned.m16n8k16.row.col.f32.f16.f16.f32 "
        "{%0,%1,%2,%3}, {%4,%5,%6,%7}, {%8,%9}, {%0,%1,%2,%3};"
        : "+f"(c[0]), "+f"(c[1]), "+f"(c[2]), "+f"(c[3])
        : "r"(a0), "r"(a1), "r"(a2), "r"(a3), "r"(b0), "r"(b1));
}

// software grid barrier (all NBLK CTAs resident: 128 <= 148 SMs, 1 CTA/SM)
__device__ __forceinline__ void grid_sync() {
    __syncthreads();
    if (threadIdx.x == 0) {
        unsigned gen;
        asm volatile("ld.volatile.global.u32 %0, [%1];" : "=r"(gen) : "l"(&g_gen));
        unsigned arr;
        asm volatile("atom.release.gpu.global.add.u32 %0, [%1], %2;"
                     : "=r"(arr) : "l"(&g_count), "r"(1u));
        if (arr == NBLK - 1) {
            *(volatile unsigned*)&g_count = 0;
            asm volatile("red.release.gpu.global.add.u32 [%0], %1;"
                         :: "l"(&g_gen), "r"(1u));
        } else {
            unsigned cur;
            do {
                asm volatile("ld.acquire.gpu.global.u32 %0, [%1];"
                             : "=r"(cur) : "l"(&g_gen));
            } while (cur == gen);
        }
    }
    __syncthreads();
}

// ---------------- packing / init kernels ----------------
// Packed layout per layer: Wp[((bc*S + s)*32 + col)*32 + kk], col = gate*8 + nl,
// row = gate*1024 + bc*8 + nl, k = s*32 + kk.  Stored [col][k] within a 32x32 stage tile.
__global__ void pack_weights(const float* __restrict__ Wih, const float* __restrict__ Whh,
                             int layer, int Kin, int S) {
    __half* Wp = (layer == 0) ? g_Wp0 : (layer == 1) ? g_Wp1 : g_Wp2;
    int idx = blockIdx.x * blockDim.x + threadIdx.x;
    int total = 128 * S * 1024;
    if (idx >= total) return;
    int kk   = idx & 31;
    int col  = (idx >> 5) & 31;
    int rest = idx >> 10;
    int s    = rest % S;
    int bc   = rest / S;
    int row  = ((col >> 3) << 10) + bc * 8 + (col & 7);
    int k    = s * 32 + kk;
    float v  = (k < Kin) ? Wih[row * Kin + k] : Whh[row * 1024 + (k - Kin)];
    Wp[idx]  = __float2half(v);
}

__global__ void init_state(const float* __restrict__ x, const float* __restrict__ h0,
                           const float* __restrict__ c0,
                           const float* __restrict__ bih0, const float* __restrict__ bhh0,
                           const float* __restrict__ bih1, const float* __restrict__ bhh1,
                           const float* __restrict__ bih2, const float* __restrict__ bhh2,
                           float* __restrict__ out) {
    int i = blockIdx.x * blockDim.x + threadIdx.x;
    if (i < 8192) { float v = x[i]; g_In0[i] = __float2half(v); out[i] = v; }
    if (i < 3 * 65536) {
        g_Hst[i >> 16][0][i & 65535] = __float2half(h0[i]);
        g_Cst[i] = c0[i];
    }
    if (i < 4096) {
        g_bsum[i]        = bih0[i] + bhh0[i];
        g_bsum[4096 + i] = bih1[i] + bhh1[i];
        g_bsum[8192 + i] = bih2[i] + bhh2[i];
    }
}

// ---------------- main persistent kernel ----------------
struct __align__(16) Smem {
    __half As[2][64 * 40];   // 64 rows x 32 k, stride 40 (conflict-free frags, 16B-aligned rows)
    __half Bs[2][32 * 40];   // 32 cols x 32 k, stride 40
    float  gates[64 * 33];
};

__device__ __forceinline__ void gemm_epi(
    Smem& sm,
    const __half* __restrict__ In, int ldIn, int stagesIn,
    const __half* __restrict__ Hp,
    const __half* __restrict__ Wblk, int stages,
    const float* __restrict__ bsumL, float* __restrict__ Cl,
    __half* __restrict__ Hnext, __half* __restrict__ Xnext,
    int tid, int bc)
{
    const int lane = tid & 31, wid = tid >> 5;
    const int rt = wid & 3;                 // row tile 0..3 (16 rows each)
    const int cb = (wid >> 2) * 16;         // column half 0 / 16
    const int ab = tid >> 2, au = tid & 3;  // A tile copy: row ab, 16B chunk au
    const int bcc = tid >> 2, bu = tid & 3; // B tile copy (threads < 128)

    float acc0[4] = {0.f, 0.f, 0.f, 0.f};
    float acc1[4] = {0.f, 0.f, 0.f, 0.f};

    auto load_stage = [&](int s, int buf) {
        const __half* src; int ld;
        if (s < stagesIn) { src = In + s * 32; ld = ldIn; }
        else              { src = Hp + (s - stagesIn) * 32; ld = 1024; }
        cp16(smaddr(&sm.As[buf][ab * 40 + au * 8]), src + ab * ld + au * 8);
        if (tid < 128)
            cp16(smaddr(&sm.Bs[buf][bcc * 40 + bu * 8]), Wblk + s * 1024 + bcc * 32 + bu * 8);
        cp_commit();
    };

    load_stage(0, 0);
    const int r  = lane >> 2;
    const int p2 = (lane & 3) * 2;
    const int aBase = (rt * 16 + r) * 40 + p2;
    const int bBase = (cb + r) * 40 + p2;

    for (int s = 0; s < stages; ++s) {
        int buf = s & 1;
        if (s + 1 < stages) {
            load_stage(s + 1, buf ^ 1);
            asm volatile("cp.async.wait_group 1;");
        } else {
            asm volatile("cp.async.wait_group 0;");
        }
        __syncthreads();
        const __half* A  = sm.As[buf];
        const __half* Bt = sm.Bs[buf];
#pragma unroll
        for (int kk = 0; kk < 2; ++kk) {
            int ko = kk * 16;
            unsigned a0 = *(const unsigned*)(A + aBase + ko);
            unsigned a1 = *(const unsigned*)(A + aBase + 320 + ko);
            unsigned a2 = *(const unsigned*)(A + aBase + ko + 8);
            unsigned a3 = *(const unsigned*)(A + aBase + 320 + ko + 8);
            unsigned b00 = *(const unsigned*)(Bt + bBase + ko);
            unsigned b01 = *(const unsigned*)(Bt + bBase + ko + 8);
            unsigned b10 = *(const unsigned*)(Bt + bBase + 320 + ko);
            unsigned b11 = *(const unsigned*)(Bt + bBase + 320 + ko + 8);
            mma16816(acc0, a0, a1, a2, a3, b00, b01);
            mma16816(acc1, a0, a1, a2, a3, b10, b11);
        }
        __syncthreads();
    }

    // store gate pre-activations to smem
    {
        int row = rt * 16 + r, col = cb + p2;
        sm.gates[row * 33 + col]           = acc0[0];
        sm.gates[row * 33 + col + 1]       = acc0[1];
        sm.gates[(row + 8) * 33 + col]     = acc0[2];
        sm.gates[(row + 8) * 33 + col + 1] = acc0[3];
        sm.gates[row * 33 + col + 8]       = acc1[0];
        sm.gates[row * 33 + col + 9]       = acc1[1];
        sm.gates[(row + 8) * 33 + col + 8] = acc1[2];
        sm.gates[(row + 8) * 33 + col + 9] = acc1[3];
    }
    __syncthreads();

    // fused LSTM cell epilogue: cols = gate*8 + nl
#pragma unroll
    for (int q = tid; q < 512; q += 256) {
        int b = q >> 3, nl = q & 7;
        int ng = bc * 8 + nl;
        float gi = sm.gates[b * 33 + nl]       + bsumL[ng];
        float gf = sm.gates[b * 33 + 8 + nl]   + bsumL[1024 + ng];
        float gg = sm.gates[b * 33 + 16 + nl]  + bsumL[2048 + ng];
        float go = sm.gates[b * 33 + 24 + nl]  + bsumL[3072 + ng];
        float c  = Cl[b * 1024 + ng];
        float cn = sigf(gf) * c + sigf(gi) * tanhf(gg);
        float h  = sigf(go) * tanhf(cn);
        Cl[b * 1024 + ng] = cn;
        __half hh = __float2half(h);
        Hnext[b * 1024 + ng] = hh;
        Xnext[b * 1024 + ng] = hh;
    }
}

__global__ void __launch_bounds__(NTHR, 1)
lstm_main(const float* __restrict__ x, const float* __restrict__ Wfc,
          const float* __restrict__ bfc, float* __restrict__ out)
{
    __shared__ Smem sm;
    const int tid = threadIdx.x, bc = blockIdx.x;

#pragma unroll 1
    for (int t = 0; t < T_STEPS - 1; ++t) {
        int p = t & 1;
        gemm_epi(sm, g_In0, 128, 4, g_Hst[0][p], g_Wp0 + bc * 36 * 1024, 36,
                 g_bsum, g_Cst, g_Hst[0][p ^ 1], g_X1, tid, bc);
        grid_sync();
        gemm_epi(sm, g_X1, 1024, 32, g_Hst[1][p], g_Wp1 + bc * 64 * 1024, 64,
                 g_bsum + 4096, g_Cst + 65536, g_Hst[1][p ^ 1], g_X2, tid, bc);
        grid_sync();
        gemm_epi(sm, g_X2, 1024, 32, g_Hst[2][p], g_Wp2 + bc * 64 * 1024, 64,
                 g_bsum + 8192, g_Cst + 131072, g_Hst[2][p ^ 1], g_Xfc, tid, bc);
        grid_sync();

        // fc: out = sigmoid(h2 @ Wfc^T + bfc); blocks tile 8(batch) x 16(cols)
        {
            int br = bc >> 4, cg = bc & 15;
            int o = tid >> 2, part = tid & 3;
            int b = br * 8 + (o >> 3);
            int d = cg * 8 + (o & 7);
            const __half* hp = g_Xfc + b * 1024 + part * 256;
            const float*  wp = Wfc + d * 1024 + part * 256;
            float a0 = 0.f, a1 = 0.f, a2 = 0.f, a3 = 0.f;
#pragma unroll 8
            for (int k = 0; k < 256; k += 4) {
                a0 += __half2float(hp[k])     * wp[k];
                a1 += __half2float(hp[k + 1]) * wp[k + 1];
                a2 += __half2float(hp[k + 2]) * wp[k + 2];
                a3 += __half2float(hp[k + 3]) * wp[k + 3];
            }
            float acc = (a0 + a1) + (a2 + a3);
            acc += __shfl_xor_sync(0xffffffff, acc, 1);
            acc += __shfl_xor_sync(0xffffffff, acc, 2);
            if (part == 0) {
                float z = sigf(acc + bfc[d]);
                float v = (t + 1 < PLEN) ? x[(size_t)(t + 1) * 8192 + b * 128 + d] : z;
                out[(size_t)(t + 1) * 8192 + b * 128 + d] = v;
                g_In0[b * 128 + d] = __float2half(v);
            }
        }
        grid_sync();
    }
}

// ---------------- launch ----------------
extern "C" void kernel_launch(void* const* d_in, const int* in_sizes, int n_in,
                              void* d_out, int out_size) {
    const float* x    = (const float*)d_in[0];
    const float* h0   = (const float*)d_in[1];
    const float* c0   = (const float*)d_in[2];
    const float* Wih0 = (const float*)d_in[3];
    const float* Whh0 = (const float*)d_in[4];
    const float* bih0 = (const float*)d_in[5];
    const float* bhh0 = (const float*)d_in[6];
    const float* Wih1 = (const float*)d_in[7];
    const float* Whh1 = (const float*)d_in[8];
    const float* bih1 = (const float*)d_in[9];
    const float* bhh1 = (const float*)d_in[10];
    const float* Wih2 = (const float*)d_in[11];
    const float* Whh2 = (const float*)d_in[12];
    const float* bih2 = (const float*)d_in[13];
    const float* bhh2 = (const float*)d_in[14];
    const float* Wfc  = (const float*)d_in[15];
    const float* bfc  = (const float*)d_in[16];
    float* out = (float*)d_out;

    pack_weights<<<(128 * 36 * 1024 + 255) / 256, 256>>>(Wih0, Whh0, 0, 128, 36);
    pack_weights<<<(128 * 64 * 1024 + 255) / 256, 256>>>(Wih1, Whh1, 1, 1024, 64);
    pack_weights<<<(128 * 64 * 1024 + 255) / 256, 256>>>(Wih2, Whh2, 2, 1024, 64);
    init_state<<<768, 256>>>(x, h0, c0, bih0, bhh0, bih1, bhh1, bih2, bhh2, out);
    lstm_main<<<NBLK, NTHR>>>(x, Wfc, bfc, out);
}

// round 3
// speedup vs baseline: 2.3518x; 2.3518x over previous
#include <cuda_runtime.h>
#include <cuda_fp16.h>

#define NBLK 128
#define NTHR 256
#define T_STEPS 512
#define PLEN 64

#define BK 64                 // k-halves per stage
#define RING 4                // cp.async pipeline depth
#define SA 72                 // smem row stride (halves), conflict-free + 16B aligned
#define ASTAGE (64 * SA)      // halves per A stage
#define BSTAGE (32 * SA)      // halves per B stage
#define SMEM_BYTES (RING * (ASTAGE + BSTAGE) * 2 + 64 * 33 * 4)

// ---------------- device state (no allocations allowed) ----------------
__device__ __half g_Wp0[128 * 18 * 2048];   // layer0 packed fp16 (K=1152 -> 18 stages)
__device__ __half g_Wp1[128 * 32 * 2048];   // layer1 packed (K=2048 -> 32 stages)
__device__ __half g_Wp2[128 * 32 * 2048];   // layer2 packed
__device__ __half g_Wfch[128 * 1024];       // fc weights fp16
__device__ float  g_bsum[3 * 4096];
__device__ __half g_In0[64 * 128];          // layer0 input slice (fp16)
__device__ __half g_X1[64 * 1024];          // h0(t) -> layer1 input
__device__ __half g_X2[64 * 1024];          // h1(t) -> layer2 input
__device__ __half g_Xfc[64 * 1024];         // h2(t) -> fc input
__device__ __half g_Hst[3][2][64 * 1024];   // double-buffered recurrent h
__device__ float  g_Cst[3 * 64 * 1024];     // cell state fp32
__device__ unsigned g_count;
__device__ unsigned g_gen;

// ---------------- helpers ----------------
__device__ __forceinline__ float sigf(float v) { return 1.0f / (1.0f + expf(-v)); }

__device__ __forceinline__ unsigned smaddr(const void* p) {
    return (unsigned)__cvta_generic_to_shared(p);
}
__device__ __forceinline__ void cp16(unsigned dst, const void* src) {
    asm volatile("cp.async.cg.shared.global [%0], [%1], 16;" :: "r"(dst), "l"(src));
}
__device__ __forceinline__ void cp_commit() { asm volatile("cp.async.commit_group;"); }

__device__ __forceinline__ void ldsm4(unsigned& r0, unsigned& r1, unsigned& r2, unsigned& r3,
                                      unsigned addr) {
    asm volatile("ldmatrix.sync.aligned.m8n8.x4.shared.b16 {%0,%1,%2,%3}, [%4];"
                 : "=r"(r0), "=r"(r1), "=r"(r2), "=r"(r3) : "r"(addr));
}

__device__ __forceinline__ void mma16816(float c[4],
    unsigned a0, unsigned a1, unsigned a2, unsigned a3, unsigned b0, unsigned b1) {
    asm volatile(
        "mma.sync.aligned.m16n8k16.row.col.f32.f16.f16.f32 "
        "{%0,%1,%2,%3}, {%4,%5,%6,%7}, {%8,%9}, {%0,%1,%2,%3};"
        : "+f"(c[0]), "+f"(c[1]), "+f"(c[2]), "+f"(c[3])
        : "r"(a0), "r"(a1), "r"(a2), "r"(a3), "r"(b0), "r"(b1));
}

// software grid barrier (128 CTAs, all resident)
__device__ __forceinline__ void grid_sync() {
    __syncthreads();
    if (threadIdx.x == 0) {
        unsigned gen;
        asm volatile("ld.volatile.global.u32 %0, [%1];" : "=r"(gen) : "l"(&g_gen));
        unsigned arr;
        asm volatile("atom.release.gpu.global.add.u32 %0, [%1], %2;"
                     : "=r"(arr) : "l"(&g_count), "r"(1u));
        if (arr == NBLK - 1) {
            *(volatile unsigned*)&g_count = 0;
            asm volatile("red.release.gpu.global.add.u32 [%0], %1;"
                         :: "l"(&g_gen), "r"(1u));
        } else {
            unsigned cur;
            do {
                asm volatile("ld.acquire.gpu.global.u32 %0, [%1];"
                             : "=r"(cur) : "l"(&g_gen));
            } while (cur == gen);
        }
    }
    __syncthreads();
}

// ---------------- packing / init kernels ----------------
// Packed layout: Wp[((bc*S + s)*32 + col)*64 + kk], col = gate*8 + nl,
// row = gate*1024 + bc*8 + nl, k = s*64 + kk.
__global__ void pack_weights(const float* __restrict__ Wih, const float* __restrict__ Whh,
                             int layer, int Kin, int S) {
    __half* Wp = (layer == 0) ? g_Wp0 : (layer == 1) ? g_Wp1 : g_Wp2;
    int idx = blockIdx.x * blockDim.x + threadIdx.x;
    int total = 128 * S * 2048;
    if (idx >= total) return;
    int kk   = idx & 63;
    int col  = (idx >> 6) & 31;
    int rest = idx >> 11;
    int s    = rest % S;
    int bc   = rest / S;
    int row  = ((col >> 3) << 10) + bc * 8 + (col & 7);
    int k    = s * 64 + kk;
    float v  = (k < Kin) ? Wih[row * Kin + k] : Whh[row * 1024 + (k - Kin)];
    Wp[idx]  = __float2half(v);
}

__global__ void pack_fc(const float* __restrict__ Wfc) {
    int i = blockIdx.x * blockDim.x + threadIdx.x;
    if (i < 128 * 1024) g_Wfch[i] = __float2half(Wfc[i]);
}

__global__ void init_state(const float* __restrict__ x, const float* __restrict__ h0,
                           const float* __restrict__ c0,
                           const float* __restrict__ bih0, const float* __restrict__ bhh0,
                           const float* __restrict__ bih1, const float* __restrict__ bhh1,
                           const float* __restrict__ bih2, const float* __restrict__ bhh2,
                           float* __restrict__ out) {
    int i = blockIdx.x * blockDim.x + threadIdx.x;
    if (i < 8192) { float v = x[i]; g_In0[i] = __float2half(v); out[i] = v; }
    if (i < 3 * 65536) {
        g_Hst[i >> 16][0][i & 65535] = __float2half(h0[i]);
        g_Cst[i] = c0[i];
    }
    if (i < 4096) {
        g_bsum[i]        = bih0[i] + bhh0[i];
        g_bsum[4096 + i] = bih1[i] + bhh1[i];
        g_bsum[8192 + i] = bih2[i] + bhh2[i];
    }
}

// ---------------- main persistent kernel ----------------
extern __shared__ __half sm_raw[];

__device__ __forceinline__ void gemm_epi(
    const __half* __restrict__ In, int ldIn, int stagesIn,
    const __half* __restrict__ Hp,
    const __half* __restrict__ Wblk, int stages,
    const float* __restrict__ bsumL, float* __restrict__ Cl,
    __half* __restrict__ Hnext, __half* __restrict__ Xnext,
    int tid, int bc)
{
    __half* As = sm_raw;                        // RING stages of 64 x SA
    __half* Bs = sm_raw + RING * ASTAGE;        // RING stages of 32 x SA
    float*  gates = (float*)(Bs + RING * BSTAGE);

    const int lane = tid & 31, wid = tid >> 5;
    const int rt = wid & 3;                 // row tile (16 rows)
    const int cb = (wid >> 2) * 16;         // col half

    // copy indices: A chunks (64 rows x 8 x 16B), threads do chunk tid, tid+256
    const int ar0 = tid >> 3, au0 = tid & 7;
    const int ar1 = (tid + 256) >> 3, au1 = au0;
    // B chunks (32 cols x 8 x 16B): one per thread
    const int bcol = tid >> 3, bu = tid & 7;

    float acc0[4] = {0.f, 0.f, 0.f, 0.f};
    float acc1[4] = {0.f, 0.f, 0.f, 0.f};

    const unsigned AsBase = smaddr(As);
    const unsigned BsBase = smaddr(Bs);

    auto load_stage = [&](int s, int slot) {
        unsigned adst = AsBase + (unsigned)(slot * ASTAGE) * 2u;
        unsigned bdst = BsBase + (unsigned)(slot * BSTAGE) * 2u;
        const __half* src;
        int ld;
        if (s < stagesIn) { src = In + s * BK; ld = ldIn; }
        else              { src = Hp + (s - stagesIn) * BK; ld = 1024; }
        cp16(adst + (unsigned)(ar0 * SA + au0 * 8) * 2u, src + ar0 * ld + au0 * 8);
        cp16(adst + (unsigned)(ar1 * SA + au1 * 8) * 2u, src + ar1 * ld + au1 * 8);
        const __half* wsrc = Wblk + (size_t)s * 2048;
        cp16(bdst + (unsigned)(bcol * SA + bu * 8) * 2u, wsrc + bcol * 64 + bu * 8);
    };

    // per-lane ldmatrix addresses (byte offsets within a stage)
    const int aRow = rt * 16 + ((lane >> 3) & 1) * 8 + (lane & 7);
    const unsigned aOff = (unsigned)(aRow * SA + (lane >> 4) * 8) * 2u;
    const int bRow = cb + ((lane >> 4) & 1) * 8 + (lane & 7);
    const unsigned bOff = (unsigned)(bRow * SA + ((lane >> 3) & 1) * 8) * 2u;

    // prologue: fill 3 stages
#pragma unroll
    for (int s = 0; s < 3; ++s) { load_stage(s, s); cp_commit(); }

#pragma unroll 1
    for (int s = 0; s < stages; ++s) {
        asm volatile("cp.async.wait_group 2;");
        __syncthreads();
        if (s + 3 < stages) load_stage(s + 3, (s + 3) & 3);
        cp_commit();

        int slot = s & 3;
        unsigned aBase = AsBase + (unsigned)(slot * ASTAGE) * 2u + aOff;
        unsigned bBase = BsBase + (unsigned)(slot * BSTAGE) * 2u + bOff;
#pragma unroll
        for (int kk = 0; kk < 4; ++kk) {
            unsigned a0, a1, a2, a3, b00, b01, b10, b11;
            ldsm4(a0, a1, a2, a3, aBase + kk * 32u);
            ldsm4(b00, b01, b10, b11, bBase + kk * 32u);
            mma16816(acc0, a0, a1, a2, a3, b00, b01);
            mma16816(acc1, a0, a1, a2, a3, b10, b11);
        }
    }

    // store gate pre-activations to smem
    {
        int r = lane >> 2, p2 = (lane & 3) * 2;
        int row = rt * 16 + r, col = cb + p2;
        gates[row * 33 + col]           = acc0[0];
        gates[row * 33 + col + 1]       = acc0[1];
        gates[(row + 8) * 33 + col]     = acc0[2];
        gates[(row + 8) * 33 + col + 1] = acc0[3];
        gates[row * 33 + col + 8]       = acc1[0];
        gates[row * 33 + col + 9]       = acc1[1];
        gates[(row + 8) * 33 + col + 8] = acc1[2];
        gates[(row + 8) * 33 + col + 9] = acc1[3];
    }
    __syncthreads();

    // fused LSTM cell epilogue: cols = gate*8 + nl
#pragma unroll
    for (int q = tid; q < 512; q += 256) {
        int b = q >> 3, nl = q & 7;
        int ng = bc * 8 + nl;
        float gi = gates[b * 33 + nl]       + bsumL[ng];
        float gf = gates[b * 33 + 8 + nl]   + bsumL[1024 + ng];
        float gg = gates[b * 33 + 16 + nl]  + bsumL[2048 + ng];
        float go = gates[b * 33 + 24 + nl]  + bsumL[3072 + ng];
        float c  = Cl[b * 1024 + ng];
        float cn = sigf(gf) * c + sigf(gi) * tanhf(gg);
        float h  = sigf(go) * tanhf(cn);
        Cl[b * 1024 + ng] = cn;
        __half hh = __float2half(h);
        Hnext[b * 1024 + ng] = hh;
        Xnext[b * 1024 + ng] = hh;
    }
}

__global__ void __launch_bounds__(NTHR, 1)
lstm_main(const float* __restrict__ x, const float* __restrict__ bfc,
          float* __restrict__ out)
{
    const int tid = threadIdx.x, bc = blockIdx.x;

#pragma unroll 1
    for (int t = 0; t < T_STEPS - 1; ++t) {
        int p = t & 1;
        gemm_epi(g_In0, 128, 2, g_Hst[0][p], g_Wp0 + (size_t)bc * 18 * 2048, 18,
                 g_bsum, g_Cst, g_Hst[0][p ^ 1], g_X1, tid, bc);
        grid_sync();
        gemm_epi(g_X1, 1024, 16, g_Hst[1][p], g_Wp1 + (size_t)bc * 32 * 2048, 32,
                 g_bsum + 4096, g_Cst + 65536, g_Hst[1][p ^ 1], g_X2, tid, bc);
        grid_sync();
        gemm_epi(g_X2, 1024, 16, g_Hst[2][p], g_Wp2 + (size_t)bc * 32 * 2048, 32,
                 g_bsum + 8192, g_Cst + 131072, g_Hst[2][p ^ 1], g_Xfc, tid, bc);
        grid_sync();

        // fc: out = sigmoid(h2 @ Wfc^T + bfc); blocks tile 8(batch) x 16(cols)
        {
            int br = bc >> 4, cg = bc & 15;
            int o = tid >> 2, part = tid & 3;
            int b = br * 8 + (o >> 3);
            int d = cg * 8 + (o & 7);
            const float4* hp = (const float4*)(g_Xfc + b * 1024) + part * 32;
            const float4* wp = (const float4*)(g_Wfch + d * 1024) + part * 32;
            float acc = 0.f;
#pragma unroll
            for (int k = 0; k < 32; ++k) {
                float4 hv = __ldcg(hp + k);
                float4 wv = __ldcg(wp + k);
                const __half2* h2 = (const __half2*)&hv;
                const __half2* w2 = (const __half2*)&wv;
#pragma unroll
                for (int j = 0; j < 4; ++j) {
                    float2 hf = __half22float2(h2[j]);
                    float2 wf = __half22float2(w2[j]);
                    acc = fmaf(hf.x, wf.x, acc);
                    acc = fmaf(hf.y, wf.y, acc);
                }
            }
            acc += __shfl_xor_sync(0xffffffff, acc, 1);
            acc += __shfl_xor_sync(0xffffffff, acc, 2);
            if (part == 0) {
                float z = sigf(acc + bfc[d]);
                float v = (t + 1 < PLEN) ? x[(size_t)(t + 1) * 8192 + b * 128 + d] : z;
                out[(size_t)(t + 1) * 8192 + b * 128 + d] = v;
                g_In0[b * 128 + d] = __float2half(v);
            }
        }
        grid_sync();
    }
}

// ---------------- launch ----------------
extern "C" void kernel_launch(void* const* d_in, const int* in_sizes, int n_in,
                              void* d_out, int out_size) {
    const float* x    = (const float*)d_in[0];
    const float* h0   = (const float*)d_in[1];
    const float* c0   = (const float*)d_in[2];
    const float* Wih0 = (const float*)d_in[3];
    const float* Whh0 = (const float*)d_in[4];
    const float* bih0 = (const float*)d_in[5];
    const float* bhh0 = (const float*)d_in[6];
    const float* Wih1 = (const float*)d_in[7];
    const float* Whh1 = (const float*)d_in[8];
    const float* bih1 = (const float*)d_in[9];
    const float* bhh1 = (const float*)d_in[10];
    const float* Wih2 = (const float*)d_in[11];
    const float* Whh2 = (const float*)d_in[12];
    const float* bih2 = (const float*)d_in[13];
    const float* bhh2 = (const float*)d_in[14];
    const float* Wfc  = (const float*)d_in[15];
    const float* bfc  = (const float*)d_in[16];
    float* out = (float*)d_out;

    static bool attr_done = false;
    if (!attr_done) {
        cudaFuncSetAttribute(lstm_main, cudaFuncAttributeMaxDynamicSharedMemorySize,
                             SMEM_BYTES);
        attr_done = true;
    }

    pack_weights<<<(128 * 18 * 2048 + 255) / 256, 256>>>(Wih0, Whh0, 0, 128, 18);
    pack_weights<<<(128 * 32 * 2048 + 255) / 256, 256>>>(Wih1, Whh1, 1, 1024, 32);
    pack_weights<<<(128 * 32 * 2048 + 255) / 256, 256>>>(Wih2, Whh2, 2, 1024, 32);
    pack_fc<<<512, 256>>>(Wfc);
    init_state<<<768, 256>>>(x, h0, c0, bih0, bhh0, bih1, bhh1, bih2, bhh2, out);
    lstm_main<<<NBLK, NTHR, SMEM_BYTES>>>(x, bfc, out);
}